// round 2
// baseline (speedup 1.0000x reference)
#include <cuda_runtime.h>

#define NB 1024           // batch
#define ND 128            // dim
#define TILE 64
#define NBLK (NB / TILE)  // 16

#define XS_STRIDE 132     // 64 rows x (128 + 4 pad) floats, float4-aligned stride
#define YS_STRIDE 68      // 128 k-rows x (64 + 4 pad) floats
#define SMEM_FLOATS (TILE * XS_STRIDE + ND * YS_STRIDE + 4 * TILE)
#define SMEM_BYTES (SMEM_FLOATS * 4)

// Deterministic cross-block partials (no fp atomics).
__device__ float g_part[NBLK * NB];   // [j_block][i] partial row sums of exp(sim)
__device__ float g_pos[NB];           // diagonal sim values

__global__ __launch_bounds__(256) void hyp_pair_kernel(const float* __restrict__ z1,
                                                       const float* __restrict__ z2) {
  extern __shared__ float sm[];
  float* xs  = sm;                      // [64][132] row-major (i, k)
  float* ys  = sm + TILE * XS_STRIDE;   // [128][68] k-major (k, j) with xor-swizzled j-blocks
  float* sn1 = ys + ND * YS_STRIDE;     // [64] squared norms of x rows
  float* srn1 = sn1 + TILE;             // [64] 1/max(sqrt(n1),1e-12)
  float* sn2 = srn1 + TILE;
  float* srn2 = sn2 + TILE;

  const int tid = threadIdx.x;
  const int tx = tid & 15;   // j direction (4 cols per thread)
  const int ty = tid >> 4;   // i direction (4 rows per thread)
  const int i0 = blockIdx.y * TILE;
  const int j0 = blockIdx.x * TILE;

  // ---- load x tile: 64x128 floats, row-major, coalesced float4 ----
  #pragma unroll
  for (int it = 0; it < 8; ++it) {
    int idx = tid + it * 256;
    int r = idx >> 5;        // row within tile
    int k4 = idx & 31;       // float4 index along k
    float4 v = reinterpret_cast<const float4*>(z1 + (size_t)(i0 + r) * ND)[k4];
    *reinterpret_cast<float4*>(xs + r * XS_STRIDE + k4 * 4) = v;
  }
  // ---- load y tile transposed to (k, j), xor-swizzle j float4-block by (k>>2)&15 ----
  #pragma unroll
  for (int it = 0; it < 8; ++it) {
    int idx = tid + it * 256;
    int r = idx >> 5;        // j within tile
    int k4 = idx & 31;
    float4 v = reinterpret_cast<const float4*>(z2 + (size_t)(j0 + r) * ND)[k4];
    int jb = r >> 2, jl = r & 3;
    int col = 4 * (jb ^ (k4 & 15)) + jl;
    ys[(4 * k4 + 0) * YS_STRIDE + col] = v.x;
    ys[(4 * k4 + 1) * YS_STRIDE + col] = v.y;
    ys[(4 * k4 + 2) * YS_STRIDE + col] = v.z;
    ys[(4 * k4 + 3) * YS_STRIDE + col] = v.w;
  }
  __syncthreads();

  // ---- per-block recompute of row norms from shared tiles (deterministic) ----
  if (tid < TILE) {
    float s = 0.f;
    #pragma unroll
    for (int k = 0; k < ND; k += 4) {
      float4 v = *reinterpret_cast<const float4*>(xs + tid * XS_STRIDE + k);
      s += v.x * v.x + v.y * v.y + v.z * v.z + v.w * v.w;
    }
    sn1[tid] = s;
    srn1[tid] = 1.0f / fmaxf(sqrtf(s), 1e-12f);
  } else if (tid < 2 * TILE) {
    int j = tid - TILE;
    int jb = j >> 2, jl = j & 3;
    float s = 0.f;
    #pragma unroll 4
    for (int k = 0; k < ND; ++k) {
      float y = ys[k * YS_STRIDE + 4 * (jb ^ ((k >> 2) & 15)) + jl];
      s += y * y;
    }
    sn2[j] = s;
    srn2[j] = 1.0f / fmaxf(sqrtf(s), 1e-12f);
  }
  __syncthreads();

  // ---- main GEMM loop: acc[ii][jj] = dot(z1[i0+4ty+ii], z2[j0+4tx+jj]) ----
  float acc[4][4];
  #pragma unroll
  for (int a = 0; a < 4; ++a)
    #pragma unroll
    for (int b = 0; b < 4; ++b) acc[a][b] = 0.f;

  #pragma unroll 4
  for (int k4 = 0; k4 < 32; ++k4) {
    const int c = 4 * (tx ^ (k4 & 15));
    float4 x4[4];
    #pragma unroll
    for (int ii = 0; ii < 4; ++ii)
      x4[ii] = *reinterpret_cast<const float4*>(xs + (4 * ty + ii) * XS_STRIDE + 4 * k4);
    #pragma unroll
    for (int m = 0; m < 4; ++m) {
      float4 yv = *reinterpret_cast<const float4*>(ys + (4 * k4 + m) * YS_STRIDE + c);
      #pragma unroll
      for (int ii = 0; ii < 4; ++ii) {
        float xv = (m == 0) ? x4[ii].x : (m == 1) ? x4[ii].y : (m == 2) ? x4[ii].z : x4[ii].w;
        acc[ii][0] = fmaf(xv, yv.x, acc[ii][0]);
        acc[ii][1] = fmaf(xv, yv.y, acc[ii][1]);
        acc[ii][2] = fmaf(xv, yv.z, acc[ii][2]);
        acc[ii][3] = fmaf(xv, yv.w, acc[ii][3]);
      }
    }
  }

  // ---- epilogue: hyperbolic distance + cosine sim + exp; per-row partial sums ----
  const float CC  = 0.05f;
  const float SQC = 0.22360679774997896f;          // sqrt(c)
  const float KD  = 22.360679774997896f;           // 5/sqrt(c): 0.5*(2/sqrt_c)*(1/T)*0.5 factored with L
  const int ibase = i0 + 4 * ty;
  const int jbase = j0 + 4 * tx;

  #pragma unroll
  for (int ii = 0; ii < 4; ++ii) {
    const float n1 = sn1[4 * ty + ii];
    const float rn1 = srn1[4 * ty + ii];
    float rs = 0.f;
    #pragma unroll
    for (int jj = 0; jj < 4; ++jj) {
      const float g  = acc[ii][jj];
      const float n2 = sn2[4 * tx + jj];
      const float rn2 = srn2[4 * tx + jj];
      const float xy = -g;                               // dot(-z1_i, z2_j)
      const float A  = fmaf(0.1f, xy, fmaf(CC, n2, 1.0f));       // 1 + 2c*xy + c*y2
      const float Bf = 1.0f - CC * n1;                           // 1 - c*x2
      const float den = fmaxf(fmaf(0.1f, xy, fmaf(CC * CC, n1 * n2, 1.0f)), 1e-6f);
      const float num2 = A * A * n1 + Bf * Bf * n2 + 2.0f * A * Bf * xy;
      const float mn = __fdividef(sqrtf(fmaxf(num2, 0.0f)), den);
      const float a = fminf(SQC * mn, 1.0f - 1e-6f);
      // atanh(a) = 0.5*log((1+a)/(1-a)); sim = 0.5*(-d/T) + 0.5*(cos/T)
      const float L = __logf(__fdividef(1.0f + a, 1.0f - a));
      const float sim = fmaf(5.0f * g, rn1 * rn2, -KD * L);
      if (ibase + ii == jbase + jj) {
        g_pos[ibase + ii] = sim;
      } else {
        rs += __expf(sim);
      }
    }
    // reduce the 16 tx-lanes of this half-warp (one i row)
    rs += __shfl_down_sync(0xffffffffu, rs, 8, 16);
    rs += __shfl_down_sync(0xffffffffu, rs, 4, 16);
    rs += __shfl_down_sync(0xffffffffu, rs, 2, 16);
    rs += __shfl_down_sync(0xffffffffu, rs, 1, 16);
    if (tx == 0) g_part[blockIdx.x * NB + ibase + ii] = rs;
  }
}

__global__ __launch_bounds__(NB) void hyp_loss_kernel(float* __restrict__ out) {
  __shared__ float red[32];
  const int i = threadIdx.x;
  float s = 0.f;
  #pragma unroll
  for (int jb = 0; jb < NBLK; ++jb) s += g_part[jb * NB + i];
  float t = logf(s) - g_pos[i];
  #pragma unroll
  for (int off = 16; off > 0; off >>= 1) t += __shfl_down_sync(0xffffffffu, t, off);
  if ((i & 31) == 0) red[i >> 5] = t;
  __syncthreads();
  if (i < 32) {
    float v = red[i];
    #pragma unroll
    for (int off = 16; off > 0; off >>= 1) v += __shfl_down_sync(0xffffffffu, v, off);
    if (i == 0) out[0] = v * (1.0f / NB);
  }
}

extern "C" void kernel_launch(void* const* d_in, const int* in_sizes, int n_in,
                              void* d_out, int out_size) {
  const float* z1 = (const float*)d_in[0];
  const float* z2 = (const float*)d_in[1];
  (void)in_sizes; (void)n_in; (void)out_size;

  // 69,632 B dynamic smem > 48 KB static limit; attribute set is capture-safe.
  cudaFuncSetAttribute(hyp_pair_kernel, cudaFuncAttributeMaxDynamicSharedMemorySize, SMEM_BYTES);

  dim3 grid(NBLK, NBLK);
  hyp_pair_kernel<<<grid, 256, SMEM_BYTES>>>(z1, z2);
  hyp_loss_kernel<<<1, NB>>>((float*)d_out);
}

// round 10
// speedup vs baseline: 1.2429x; 1.2429x over previous
#include <cuda_runtime.h>
#include <cuda_bf16.h>
#include <cstdint>

#define NB 1024
#define ND 128
#define KK 384            // packed K: A'=[hi|lo|hi], B'=[hi|hi|lo]
#define TM 128
#define TN 64
#define NIB (NB / TM)     // 8
#define NJB (NB / TN)     // 16
#define NCTA (NIB * NJB)  // 128
#define ROWB (KK * 2)     // 768 bytes per row in smem

// ---- device globals (no allocation allowed) ----
__device__ __nv_bfloat16 g_zb1[NB * KK];
__device__ __nv_bfloat16 g_zb2[NB * KK];
__device__ float g_n1[NB], g_rn1[NB], g_n2[NB], g_rn2[NB];
__device__ float g_part[NJB * NB];
__device__ float g_pos[NB];
__device__ unsigned int g_ctr = 0;

// ---- smem layout (bytes) ----
#define OFF_RP   0                    // rowpart[2][128] floats = 1024 B
#define OFF_N1   1024                 // 128 f
#define OFF_RN1  1536                 // 128 f
#define OFF_N2   2048                 // 64 f
#define OFF_RN2  2304                 // 64 f
#define OFF_RED  2560                 // 8 f
#define OFF_FLAG 2592                 // 1 int
#define OFF_A    4096                 // 128 x 768 B = 98304
#define OFF_B    (4096 + 98304)       // 64 x 768 B = 49152
#define SMEM_TOTAL (OFF_B + 49152)    // 151552 B

__device__ __forceinline__ uint32_t smem_u32(const void* p) {
  uint32_t a;
  asm("{ .reg .u64 t; cvta.to.shared.u64 t, %1; cvt.u32.u64 %0, t; }" : "=r"(a) : "l"(p));
  return a;
}
#define LDSM_X4(r0, r1, r2, r3, addr) \
  asm volatile("ldmatrix.sync.aligned.m8n8.x4.shared.b16 {%0,%1,%2,%3}, [%4];" \
               : "=r"(r0), "=r"(r1), "=r"(r2), "=r"(r3) : "r"(addr))
__device__ __forceinline__ void mma16816(float* d, const uint32_t* a, const uint32_t* b) {
  asm volatile(
      "mma.sync.aligned.m16n8k16.row.col.f32.bf16.bf16.f32 "
      "{%0,%1,%2,%3}, {%4,%5,%6,%7}, {%8,%9}, {%0,%1,%2,%3};"
      : "+f"(d[0]), "+f"(d[1]), "+f"(d[2]), "+f"(d[3])
      : "r"(a[0]), "r"(a[1]), "r"(a[2]), "r"(a[3]), "r"(b[0]), "r"(b[1]));
}
__device__ __forceinline__ uint32_t pack_bf2(__nv_bfloat16 a, __nv_bfloat16 b) {
  return ((uint32_t)__bfloat16_as_ushort(b) << 16) | (uint32_t)__bfloat16_as_ushort(a);
}

// ============ kernel 1: fp32 -> compensated-bf16 packing + row norms ============
__global__ __launch_bounds__(256) void hyp_convert(const float* __restrict__ z1,
                                                   const float* __restrict__ z2) {
  const int gw = (blockIdx.x * 256 + threadIdx.x) >> 5;  // row id 0..2047
  const int lane = threadIdx.x & 31;
  const bool isA = gw < NB;
  const int row = isA ? gw : gw - NB;
  const float* src = isA ? z1 : z2;

  float4 v = *reinterpret_cast<const float4*>(src + (size_t)row * ND + lane * 4);
  float s = v.x * v.x + v.y * v.y + v.z * v.z + v.w * v.w;
  #pragma unroll
  for (int off = 16; off; off >>= 1) s += __shfl_xor_sync(0xffffffffu, s, off);

  float xv[4] = {v.x, v.y, v.z, v.w};
  __nv_bfloat16 h[4], l[4];
  #pragma unroll
  for (int i = 0; i < 4; ++i) {
    h[i] = __float2bfloat16_rn(xv[i]);
    l[i] = __float2bfloat16_rn(xv[i] - __bfloat162float(h[i]));
  }
  uint2 hp = make_uint2(pack_bf2(h[0], h[1]), pack_bf2(h[2], h[3]));
  uint2 lp = make_uint2(pack_bf2(l[0], l[1]), pack_bf2(l[2], l[3]));

  __nv_bfloat16* dst = isA ? g_zb1 : g_zb2;
  const size_t base = (size_t)row * KK + lane * 4;
  *reinterpret_cast<uint2*>(dst + base) = hp;                   // seg0: hi
  *reinterpret_cast<uint2*>(dst + base + 128) = isA ? lp : hp;  // seg1: lo(A)/hi(B)
  *reinterpret_cast<uint2*>(dst + base + 256) = isA ? hp : lp;  // seg2: hi(A)/lo(B)

  if (lane == 0) {
    (isA ? g_n1 : g_n2)[row] = s;
    (isA ? g_rn1 : g_rn2)[row] = 1.0f / fmaxf(sqrtf(s), 1e-12f);
  }
}

// ============ kernel 2: mma.sync GEMM + fused epilogue + fused final reduce ============
__global__ __launch_bounds__(256, 1) void hyp_mma(float* __restrict__ out) {
  extern __shared__ char sm[];
  const uint32_t smb = smem_u32(sm);
  float* rowpart = reinterpret_cast<float*>(sm + OFF_RP);   // [2][128]
  float* sn1 = reinterpret_cast<float*>(sm + OFF_N1);
  float* srn1 = reinterpret_cast<float*>(sm + OFF_RN1);
  float* sn2 = reinterpret_cast<float*>(sm + OFF_N2);
  float* srn2 = reinterpret_cast<float*>(sm + OFF_RN2);
  float* red = reinterpret_cast<float*>(sm + OFF_RED);
  int* flag = reinterpret_cast<int*>(sm + OFF_FLAG);

  const int tid = threadIdx.x;
  const int wid = tid >> 5;
  const int lane = tid & 31;
  const int wi = wid & 3;        // warp i-position (4)
  const int wj = wid >> 2;       // warp j-position (2)
  const int jb = blockIdx.x;     // 0..15
  const int ib = blockIdx.y;     // 0..7
  const int i0 = ib * TM;
  const int j0 = jb * TN;

  // ---- stage A tile: 128 rows x 48 16B-chunks, XOR-swizzled by row&7 ----
  #pragma unroll
  for (int it = 0; it < 24; ++it) {
    int idx = tid + it * 256;
    int r = idx / 48, c = idx - r * 48;
    uint4 v = *reinterpret_cast<const uint4*>(g_zb1 + (size_t)(i0 + r) * KK + c * 8);
    *reinterpret_cast<uint4*>(sm + OFF_A + r * ROWB + (c ^ (r & 7)) * 16) = v;
  }
  // ---- stage B tile: 64 rows x 48 chunks ----
  #pragma unroll
  for (int it = 0; it < 12; ++it) {
    int idx = tid + it * 256;
    int r = idx / 48, c = idx - r * 48;
    uint4 v = *reinterpret_cast<const uint4*>(g_zb2 + (size_t)(j0 + r) * KK + c * 8);
    *reinterpret_cast<uint4*>(sm + OFF_B + r * ROWB + (c ^ (r & 7)) * 16) = v;
  }
  // ---- stage norms ----
  if (tid < TM) { sn1[tid] = g_n1[i0 + tid]; srn1[tid] = g_rn1[i0 + tid]; }
  else if (tid < TM + TN) {
    int j = tid - TM;
    sn2[j] = g_n2[j0 + j]; srn2[j] = g_rn2[j0 + j];
  }
  __syncthreads();

  // ---- per-lane ldmatrix addressing ----
  const uint32_t sx = lane & 7;                 // swizzle xor (row&7, same for A and B)
  const int akof8 = lane >> 4;                  // A: k-half selector
  const int bkof8 = (lane >> 3) & 1;            // B: k-half selector
  uint32_t aoff[2], boff[2];
  #pragma unroll
  for (int a = 0; a < 2; ++a) {
    int row = wi * 32 + a * 16 + (lane & 15);
    aoff[a] = smb + OFF_A + row * ROWB;
  }
  #pragma unroll
  for (int nt = 0; nt < 2; ++nt) {
    int nrow = wj * 32 + nt * 16 + (lane & 7) + ((lane >> 4) << 3);
    boff[nt] = smb + OFF_B + nrow * ROWB;
  }

  float acc[2][4][4];
  #pragma unroll
  for (int a = 0; a < 2; ++a)
    #pragma unroll
    for (int n = 0; n < 4; ++n)
      #pragma unroll
      for (int e = 0; e < 4; ++e) acc[a][n][e] = 0.f;

  // ---- main loop: 24 k16 steps over packed K=384 ----
  #pragma unroll 8
  for (int ks = 0; ks < 24; ++ks) {
    uint32_t ar[2][4], br[2][4];
    #pragma unroll
    for (int a = 0; a < 2; ++a) {
      uint32_t ad = aoff[a] + (((ks * 2 + akof8) ^ sx) << 4);
      LDSM_X4(ar[a][0], ar[a][1], ar[a][2], ar[a][3], ad);
    }
    #pragma unroll
    for (int nt = 0; nt < 2; ++nt) {
      uint32_t bd = boff[nt] + (((ks * 2 + bkof8) ^ sx) << 4);
      LDSM_X4(br[nt][0], br[nt][1], br[nt][2], br[nt][3], bd);
    }
    #pragma unroll
    for (int a = 0; a < 2; ++a) {
      mma16816(acc[a][0], ar[a], &br[0][0]);
      mma16816(acc[a][1], ar[a], &br[0][2]);
      mma16816(acc[a][2], ar[a], &br[1][0]);
      mma16816(acc[a][3], ar[a], &br[1][2]);
    }
  }

  // ---- epilogue: hyperbolic + cosine sim, exp, per-row partial sums ----
  const int tg = lane >> 2;   // row within octet
  const int tl = lane & 3;    // column group
  const float CC = 0.05f, SQC = 0.22360679774997896f, KD = 22.360679774997896f;

  #pragma unroll
  for (int a = 0; a < 2; ++a) {
    #pragma unroll
    for (int h = 0; h < 2; ++h) {
      const int rowl = wi * 32 + a * 16 + h * 8 + tg;
      const int ig = i0 + rowl;
      const float n1 = sn1[rowl];
      const float rn1 = srn1[rowl];
      float rs = 0.f;
      #pragma unroll
      for (int ni = 0; ni < 4; ++ni) {
        #pragma unroll
        for (int e = 0; e < 2; ++e) {
          const int col = wj * 32 + ni * 8 + tl * 2 + e;
          const float g = acc[a][ni][h * 2 + e];
          const float n2 = sn2[col];
          const float xy = -g;
          const float Af = fmaf(0.1f, xy, fmaf(CC, n2, 1.0f));
          const float Bf = 1.0f - CC * n1;
          const float den = fmaxf(fmaf(0.1f, xy, fmaf(CC * CC, n1 * n2, 1.0f)), 1e-6f);
          const float num2 = Af * Af * n1 + Bf * Bf * n2 + 2.0f * Af * Bf * xy;
          const float s = SQC * sqrtf(fmaxf(num2, 0.0f));
          float r = __fdividef(den + s, fmaxf(den - s, 1e-6f * den));
          r = fminf(r, 2.0e6f);
          const float sim = fmaf(5.0f * g, rn1 * srn2[col], -KD * __logf(r));
          if (ig == j0 + col) g_pos[ig] = sim;
          else rs += __expf(sim);
        }
      }
      rs += __shfl_xor_sync(0xffffffffu, rs, 1);
      rs += __shfl_xor_sync(0xffffffffu, rs, 2);
      if (tl == 0) rowpart[wj * TM + rowl] = rs;
    }
  }
  __syncthreads();
  if (tid < TM) g_part[jb * NB + i0 + tid] = rowpart[tid] + rowpart[TM + tid];

  // ---- last-CTA fused final reduction (deterministic order) ----
  __threadfence();
  __syncthreads();
  if (tid == 0) {
    unsigned t = atomicAdd(&g_ctr, 1u);
    *flag = (t == NCTA - 1) ? 1 : 0;
  }
  __syncthreads();
  if (*flag) {
    __threadfence();
    float acc2 = 0.f;
    #pragma unroll
    for (int q = 0; q < 4; ++q) {
      const int i = tid + q * 256;
      float ssum = 0.f;
      #pragma unroll
      for (int b = 0; b < NJB; ++b) ssum += g_part[b * NB + i];
      acc2 += logf(ssum) - g_pos[i];
    }
    #pragma unroll
    for (int off = 16; off; off >>= 1) acc2 += __shfl_down_sync(0xffffffffu, acc2, off);
    if (lane == 0) red[wid] = acc2;
    __syncthreads();
    if (tid == 0) {
      float tt = 0.f;
      #pragma unroll
      for (int w = 0; w < 8; ++w) tt += red[w];
      out[0] = tt * (1.0f / NB);
      g_ctr = 0;  // reset for next graph replay
    }
  }
}

extern "C" void kernel_launch(void* const* d_in, const int* in_sizes, int n_in,
                              void* d_out, int out_size) {
  const float* z1 = (const float*)d_in[0];
  const float* z2 = (const float*)d_in[1];
  (void)in_sizes; (void)n_in; (void)out_size;

  cudaFuncSetAttribute(hyp_mma, cudaFuncAttributeMaxDynamicSharedMemorySize, SMEM_TOTAL);

  hyp_convert<<<256, 256>>>(z1, z2);
  dim3 grid(NJB, NIB);
  hyp_mma<<<grid, 256, SMEM_TOTAL>>>((float*)d_out);
}